// round 2
// baseline (speedup 1.0000x reference)
#include <cuda_runtime.h>
#include <cuda_bf16.h>
#include <math.h>
#include <stdint.h>

// ---------------------------------------------------------------------------
// Problem constants (fixed shapes from the reference)
// ---------------------------------------------------------------------------
#define HH     32          // query heads
#define KVH    8           // kv heads
#define DD     128         // head dim
#define HID    (HH * DD)   // 4096
#define NQK    (HID + 2 * KVH * DD)  // 6144
#define BB     4
#define SS     1024
#define TT     (BB * SS)   // 4096
#define CACHE  16384
#define GRP    (HH / KVH)  // 4

// ---------------------------------------------------------------------------
// Scratch (device globals; no allocations allowed)
// ---------------------------------------------------------------------------
__device__ float g_qkv[(size_t)TT * NQK];    // 100.7 MB: qkv projection (post-rope)
__device__ float g_attn[(size_t)TT * HID];   // 67 MB:  attention output (bqhd flat)
__device__ int   g_owner[CACHE];             // last-writer-wins owner per cache slot

// ---------------------------------------------------------------------------
// Split-bf16 tensor-core GEMM:
//   C[M,N] = A[M,K] * B[N,K]^T + bias[N]   (A,B row-major, K contiguous)
// fp32 x = hi(bf16) + lo(bf16); accumulate hi*hi + hi*lo + lo*hi in fp32.
// BM=BN=128, BK=32, 256 threads, 8 warps (2x4), warp tile 64x32,
// mma.sync.m16n8k16, ldmatrix from stride-40 (80B) padded smem (conflict-free).
// ---------------------------------------------------------------------------
#define GPAD 40   // bf16 elements per smem row (32 data + 8 pad)

__device__ __forceinline__ uint32_t pack_bf2(__nv_bfloat16 a, __nv_bfloat16 b) {
    return (uint32_t)__bfloat16_as_ushort(a) | ((uint32_t)__bfloat16_as_ushort(b) << 16);
}

__device__ __forceinline__ void ldsm_x4(uint32_t& r0, uint32_t& r1,
                                        uint32_t& r2, uint32_t& r3, uint32_t addr) {
    asm volatile("ldmatrix.sync.aligned.m8n8.x4.shared.b16 {%0,%1,%2,%3}, [%4];"
                 : "=r"(r0), "=r"(r1), "=r"(r2), "=r"(r3) : "r"(addr));
}

__device__ __forceinline__ void mma16816(float* d, const uint32_t* a, const uint32_t* b) {
    asm volatile("mma.sync.aligned.m16n8k16.row.col.f32.bf16.bf16.f32 "
                 "{%0,%1,%2,%3}, {%4,%5,%6,%7}, {%8,%9}, {%0,%1,%2,%3};"
                 : "+f"(d[0]), "+f"(d[1]), "+f"(d[2]), "+f"(d[3])
                 : "r"(a[0]), "r"(a[1]), "r"(a[2]), "r"(a[3]), "r"(b[0]), "r"(b[1]));
}

__global__ __launch_bounds__(256)
void gemm_bf16split_nt_bias(int M, int N, int K,
                            const float* __restrict__ A,
                            const float* __restrict__ B,
                            const float* __restrict__ bias,
                            float* __restrict__ C)
{
    __shared__ __align__(16) __nv_bfloat16 Ah[128 * GPAD];
    __shared__ __align__(16) __nv_bfloat16 Al[128 * GPAD];
    __shared__ __align__(16) __nv_bfloat16 Bh[128 * GPAD];
    __shared__ __align__(16) __nv_bfloat16 Bl[128 * GPAD];

    const int tid  = threadIdx.x;
    const int lane = tid & 31;
    const int wid  = tid >> 5;
    const int wm   = wid & 1;          // 0..1  (64-row strip)
    const int wn   = wid >> 1;         // 0..3  (32-col strip)
    const int bm   = blockIdx.y * 128;
    const int bn   = blockIdx.x * 128;

    const uint32_t ah_s = (uint32_t)__cvta_generic_to_shared(Ah);
    const uint32_t al_s = (uint32_t)__cvta_generic_to_shared(Al);
    const uint32_t bh_s = (uint32_t)__cvta_generic_to_shared(Bh);
    const uint32_t bl_s = (uint32_t)__cvta_generic_to_shared(Bl);

    float acc[4][4][4];
#pragma unroll
    for (int mt = 0; mt < 4; mt++)
#pragma unroll
        for (int nt = 0; nt < 4; nt++)
#pragma unroll
            for (int r = 0; r < 4; r++) acc[mt][nt][r] = 0.0f;

    // gmem prefetch registers: 4 float4 of A + 4 of B per thread per chunk
    float4 pa[4], pb[4];
#pragma unroll
    for (int l = 0; l < 4; l++) {
        int id  = tid + l * 256;        // 0..1023
        int row = id >> 3;
        int c4  = (id & 7) << 2;
        pa[l] = *reinterpret_cast<const float4*>(&A[(size_t)(bm + row) * K + c4]);
        pb[l] = *reinterpret_cast<const float4*>(&B[(size_t)(bn + row) * K + c4]);
    }

    for (int k0 = 0; k0 < K; k0 += 32) {
        // stage: convert fp32 -> (hi, lo) bf16 and store to smem
#pragma unroll
        for (int l = 0; l < 4; l++) {
            int id  = tid + l * 256;
            int row = id >> 3;
            int c4  = (id & 7) << 2;
            float x[4] = {pa[l].x, pa[l].y, pa[l].z, pa[l].w};
            __nv_bfloat16 h[4], lo[4];
#pragma unroll
            for (int e = 0; e < 4; e++) {
                h[e]  = __float2bfloat16_rn(x[e]);
                lo[e] = __float2bfloat16_rn(x[e] - __bfloat162float(h[e]));
            }
            uint32_t* hp = reinterpret_cast<uint32_t*>(&Ah[row * GPAD + c4]);
            uint32_t* lp = reinterpret_cast<uint32_t*>(&Al[row * GPAD + c4]);
            hp[0] = pack_bf2(h[0], h[1]);  hp[1] = pack_bf2(h[2], h[3]);
            lp[0] = pack_bf2(lo[0], lo[1]); lp[1] = pack_bf2(lo[2], lo[3]);

            float y[4] = {pb[l].x, pb[l].y, pb[l].z, pb[l].w};
#pragma unroll
            for (int e = 0; e < 4; e++) {
                h[e]  = __float2bfloat16_rn(y[e]);
                lo[e] = __float2bfloat16_rn(y[e] - __bfloat162float(h[e]));
            }
            hp = reinterpret_cast<uint32_t*>(&Bh[row * GPAD + c4]);
            lp = reinterpret_cast<uint32_t*>(&Bl[row * GPAD + c4]);
            hp[0] = pack_bf2(h[0], h[1]);  hp[1] = pack_bf2(h[2], h[3]);
            lp[0] = pack_bf2(lo[0], lo[1]); lp[1] = pack_bf2(lo[2], lo[3]);
        }
        __syncthreads();

        // prefetch next chunk from gmem while computing this one
        if (k0 + 32 < K) {
#pragma unroll
            for (int l = 0; l < 4; l++) {
                int id  = tid + l * 256;
                int row = id >> 3;
                int c4  = (id & 7) << 2;
                pa[l] = *reinterpret_cast<const float4*>(&A[(size_t)(bm + row) * K + k0 + 32 + c4]);
                pb[l] = *reinterpret_cast<const float4*>(&B[(size_t)(bn + row) * K + k0 + 32 + c4]);
            }
        }

        // ldmatrix lane geometry (shared by A and B loads)
        const int lrow = (lane & 7) + ((lane >> 3) & 1) * 8;   // row within 16-row tile
        const int lcol = (lane >> 4) * 8;                      // 0 or 8 (k-offset)

#pragma unroll
        for (int ks = 0; ks < 32; ks += 16) {
            uint32_t a_h[4][4], a_l[4][4], b_h[4][2], b_l[4][2];
#pragma unroll
            for (int mt = 0; mt < 4; mt++) {
                uint32_t off = (uint32_t)(((wm * 64 + mt * 16 + lrow) * GPAD + ks + lcol) * 2);
                ldsm_x4(a_h[mt][0], a_h[mt][1], a_h[mt][2], a_h[mt][3], ah_s + off);
                ldsm_x4(a_l[mt][0], a_l[mt][1], a_l[mt][2], a_l[mt][3], al_s + off);
            }
#pragma unroll
            for (int p = 0; p < 2; p++) {
                uint32_t off = (uint32_t)(((wn * 32 + p * 16 + lrow) * GPAD + ks + lcol) * 2);
                uint32_t r0, r1, r2, r3;
                ldsm_x4(r0, r1, r2, r3, bh_s + off);
                b_h[2 * p][0] = r0; b_h[2 * p][1] = r2;
                b_h[2 * p + 1][0] = r1; b_h[2 * p + 1][1] = r3;
                ldsm_x4(r0, r1, r2, r3, bl_s + off);
                b_l[2 * p][0] = r0; b_l[2 * p][1] = r2;
                b_l[2 * p + 1][0] = r1; b_l[2 * p + 1][1] = r3;
            }
#pragma unroll
            for (int mt = 0; mt < 4; mt++)
#pragma unroll
                for (int nt = 0; nt < 4; nt++) {
                    mma16816(acc[mt][nt], a_h[mt], b_h[nt]);   // hi*hi
                    mma16816(acc[mt][nt], a_h[mt], b_l[nt]);   // hi*lo
                    mma16816(acc[mt][nt], a_l[mt], b_h[nt]);   // lo*hi
                }
        }
        __syncthreads();
    }

    // epilogue: add bias, write C
#pragma unroll
    for (int mt = 0; mt < 4; mt++) {
        int row = bm + wm * 64 + mt * 16 + (lane >> 2);
#pragma unroll
        for (int nt = 0; nt < 4; nt++) {
            int col = bn + wn * 32 + nt * 8 + (lane & 3) * 2;
            float b0 = bias[col], b1 = bias[col + 1];
            float2 v0 = make_float2(acc[mt][nt][0] + b0, acc[mt][nt][1] + b1);
            float2 v1 = make_float2(acc[mt][nt][2] + b0, acc[mt][nt][3] + b1);
            *reinterpret_cast<float2*>(&C[(size_t)row * N + col])       = v0;
            *reinterpret_cast<float2*>(&C[(size_t)(row + 8) * N + col]) = v1;
        }
    }
}

// ---------------------------------------------------------------------------
// RoPE in-place on q (heads 0..31) and k (heads 32..39) of g_qkv
// ---------------------------------------------------------------------------
__global__ void rope_kernel(float* __restrict__ qkv,
                            const float* __restrict__ cosp,
                            const float* __restrict__ sinp)
{
    int idx = blockIdx.x * blockDim.x + threadIdx.x;  // TT * 40 * 64
    if (idx >= TT * 40 * 64) return;
    int i = idx & 63;
    int h = (idx >> 6) % 40;
    int t = idx / (40 * 64);
    float c = cosp[t * 64 + i];
    float s = sinp[t * 64 + i];
    float* base = qkv + (size_t)t * NQK + h * DD;
    float x1 = base[i];
    float x2 = base[i + 64];
    base[i]      = x1 * c - x2 * s;
    base[i + 64] = x2 * c + x1 * s;
}

// ---------------------------------------------------------------------------
// Cache scatter with last-writer-wins (sequential .at[].set semantics)
// ---------------------------------------------------------------------------
__global__ void owner_init_kernel()
{
    int i = blockIdx.x * blockDim.x + threadIdx.x;
    if (i < CACHE) g_owner[i] = -1;
}

__global__ void owner_scatter_kernel(const int* __restrict__ slots)
{
    int t = blockIdx.x * blockDim.x + threadIdx.x;
    if (t < TT) atomicMax(&g_owner[slots[t]], t);
}

__global__ void cache_write_kernel(const float* __restrict__ qkv,
                                   const int* __restrict__ slots,
                                   float* __restrict__ kout,
                                   float* __restrict__ vout)
{
    int idx = blockIdx.x * blockDim.x + threadIdx.x;  // TT * 1024
    if (idx >= TT * KVH * DD) return;
    int t = idx >> 10;
    int j = idx & 1023;
    int slot = slots[t];
    if (g_owner[slot] != t) return;
    kout[(size_t)slot * (KVH * DD) + j] = qkv[(size_t)t * NQK + HID + j];
    vout[(size_t)slot * (KVH * DD) + j] = qkv[(size_t)t * NQK + HID + KVH * DD + j];
}

// ---------------------------------------------------------------------------
// Flash attention (fp32), causal, GQA. One CTA = (batch, head, 64-row q tile)
// smem: Qs[128][64] Ks[128][64] Vs[64][128] Pt[64][64] + stats = 115456 B
// ---------------------------------------------------------------------------
#define ATTN_SMEM_FLOATS (128*64 + 128*64 + 64*128 + 64*64 + 3*64)
#define ATTN_SMEM_BYTES  (ATTN_SMEM_FLOATS * 4)

__global__ __launch_bounds__(256)
void attn_kernel(const float* __restrict__ qkv, float* __restrict__ attn_out)
{
    extern __shared__ float sm[];
    float* Qs   = sm;                    // [d][r]  128x64
    float* Ks   = Qs + 128 * 64;         // [d][c]  128x64
    float* Vs   = Ks + 128 * 64;         // [c][d]  64x128
    float* Pt   = Vs + 64 * 128;         // [c][r]  64x64
    float* mrow = Pt + 64 * 64;          // [64]
    float* lrow = mrow + 64;
    float* arow = lrow + 64;

    const int qt = blockIdx.x;          // 0..15
    const int h  = blockIdx.y;          // 0..31
    const int b  = blockIdx.z;          // 0..3
    const int tid = threadIdx.x;
    const int tx = tid & 15;
    const int ty = tid >> 4;

    const int qbase  = qt * 64;
    const int qoff   = h * DD;
    const int koff   = HID + (h >> 2) * DD;
    const int voff   = HID + KVH * DD + (h >> 2) * DD;
    const float scale = 0.08838834764831845f;  // 1/sqrt(128)

    // load Q tile (transposed: Qs[d][r])
#pragma unroll
    for (int l = 0; l < 8; l++) {
        int id = tid + l * 256;          // 0..2047
        int r  = id >> 5;
        int d4 = (id & 31) * 4;
        float4 v = *reinterpret_cast<const float4*>(
            &qkv[(size_t)(b * SS + qbase + r) * NQK + qoff + d4]);
        Qs[(d4 + 0) * 64 + r] = v.x;
        Qs[(d4 + 1) * 64 + r] = v.y;
        Qs[(d4 + 2) * 64 + r] = v.z;
        Qs[(d4 + 3) * 64 + r] = v.w;
    }
    if (tid < 64) { mrow[tid] = -INFINITY; lrow[tid] = 0.0f; }

    float o[4][8];
#pragma unroll
    for (int i = 0; i < 4; i++)
#pragma unroll
        for (int j = 0; j < 8; j++) o[i][j] = 0.0f;

    for (int jt = 0; jt <= qt; jt++) {
        __syncthreads();   // protect Ks/Vs/Pt from previous iteration's readers
        // load K tile (transposed) and V tile (natural)
#pragma unroll
        for (int l = 0; l < 8; l++) {
            int id = tid + l * 256;
            int r  = id >> 5;
            int d4 = (id & 31) * 4;
            float4 v = *reinterpret_cast<const float4*>(
                &qkv[(size_t)(b * SS + jt * 64 + r) * NQK + koff + d4]);
            Ks[(d4 + 0) * 64 + r] = v.x;
            Ks[(d4 + 1) * 64 + r] = v.y;
            Ks[(d4 + 2) * 64 + r] = v.z;
            Ks[(d4 + 3) * 64 + r] = v.w;
            float4 w = *reinterpret_cast<const float4*>(
                &qkv[(size_t)(b * SS + jt * 64 + r) * NQK + voff + d4]);
            *reinterpret_cast<float4*>(&Vs[r * 128 + d4]) = w;
        }
        __syncthreads();

        // S = Q K^T  (4x4 microtile per thread)
        float s[4][4];
#pragma unroll
        for (int i = 0; i < 4; i++)
#pragma unroll
            for (int j = 0; j < 4; j++) s[i][j] = 0.0f;
#pragma unroll 4
        for (int d = 0; d < 128; d++) {
            float4 qa = *reinterpret_cast<const float4*>(&Qs[d * 64 + ty * 4]);
            float4 kb = *reinterpret_cast<const float4*>(&Ks[d * 64 + tx * 4]);
            float qs[4] = {qa.x, qa.y, qa.z, qa.w};
            float ks[4] = {kb.x, kb.y, kb.z, kb.w};
#pragma unroll
            for (int i = 0; i < 4; i++)
#pragma unroll
                for (int j = 0; j < 4; j++)
                    s[i][j] = fmaf(qs[i], ks[j], s[i][j]);
        }
        // scale + causal mask, write transposed into Pt[c][r]
        const bool diag = (jt == qt);
#pragma unroll
        for (int i = 0; i < 4; i++) {
            int r = ty * 4 + i;
#pragma unroll
            for (int j = 0; j < 4; j++) {
                int c = tx * 4 + j;
                float v = s[i][j] * scale;
                if (diag && c > r) v = -1e30f;
                Pt[c * 64 + r] = v;
            }
        }
        __syncthreads();

        // softmax update: one thread per row
        if (tid < 64) {
            int r = tid;
            float mo = mrow[r];
            float mx = mo;
            for (int c = 0; c < 64; c++) mx = fmaxf(mx, Pt[c * 64 + r]);
            float sum = 0.0f;
            for (int c = 0; c < 64; c++) {
                float p = __expf(Pt[c * 64 + r] - mx);
                Pt[c * 64 + r] = p;
                sum += p;
            }
            float alpha = __expf(mo - mx);
            arow[r] = alpha;
            lrow[r] = lrow[r] * alpha + sum;
            mrow[r] = mx;
        }
        __syncthreads();

        // rescale O, then O += P V
#pragma unroll
        for (int i = 0; i < 4; i++) {
            float alpha = arow[ty * 4 + i];
#pragma unroll
            for (int j = 0; j < 8; j++) o[i][j] *= alpha;
        }
#pragma unroll 2
        for (int c = 0; c < 64; c++) {
            float4 p4 = *reinterpret_cast<const float4*>(&Pt[c * 64 + ty * 4]);
            float pv[4] = {p4.x, p4.y, p4.z, p4.w};
            float4 v0 = *reinterpret_cast<const float4*>(&Vs[c * 128 + tx * 8]);
            float4 v1 = *reinterpret_cast<const float4*>(&Vs[c * 128 + tx * 8 + 4]);
            float vv[8] = {v0.x, v0.y, v0.z, v0.w, v1.x, v1.y, v1.z, v1.w};
#pragma unroll
            for (int i = 0; i < 4; i++)
#pragma unroll
                for (int j = 0; j < 8; j++)
                    o[i][j] = fmaf(pv[i], vv[j], o[i][j]);
        }
    }
    __syncthreads();

    // normalize + store
#pragma unroll
    for (int i = 0; i < 4; i++) {
        int r = ty * 4 + i;
        float inv = 1.0f / lrow[r];
        size_t row = (size_t)(b * SS + qbase + r) * HID + h * DD + tx * 8;
        float4 o0 = make_float4(o[i][0] * inv, o[i][1] * inv, o[i][2] * inv, o[i][3] * inv);
        float4 o1 = make_float4(o[i][4] * inv, o[i][5] * inv, o[i][6] * inv, o[i][7] * inv);
        *reinterpret_cast<float4*>(&attn_out[row])     = o0;
        *reinterpret_cast<float4*>(&attn_out[row + 4]) = o1;
    }
}

// ---------------------------------------------------------------------------
// kernel_launch
// ---------------------------------------------------------------------------
extern "C" void kernel_launch(void* const* d_in, const int* in_sizes, int n_in,
                              void* d_out, int out_size)
{
    const float* hidden = (const float*)d_in[0];
    const float* cosp   = (const float*)d_in[1];
    const float* sinp   = (const float*)d_in[2];
    const float* w_qkv  = (const float*)d_in[3];
    const float* b_qkv  = (const float*)d_in[4];
    const float* w_o    = (const float*)d_in[5];
    const float* b_o    = (const float*)d_in[6];
    const float* kc_in  = (const float*)d_in[7];
    const float* vc_in  = (const float*)d_in[8];
    const int*   slots  = (const int*)d_in[9];

    float* out  = (float*)d_out;
    float* kout = out + (size_t)TT * HID;
    float* vout = kout + (size_t)CACHE * KVH * DD;

    float* qkv_buf;
    float* attn_buf;
    cudaGetSymbolAddress((void**)&qkv_buf, g_qkv);
    cudaGetSymbolAddress((void**)&attn_buf, g_attn);

    const size_t cache_bytes = (size_t)CACHE * KVH * DD * sizeof(float);
    cudaMemcpyAsync(kout, kc_in, cache_bytes, cudaMemcpyDeviceToDevice);
    cudaMemcpyAsync(vout, vc_in, cache_bytes, cudaMemcpyDeviceToDevice);

    // 1) QKV projection (tensor cores, split-bf16)
    {
        dim3 grid(NQK / 128, TT / 128);
        gemm_bf16split_nt_bias<<<grid, 256>>>(TT, NQK, HID, hidden, w_qkv, b_qkv, qkv_buf);
    }
    // 2) RoPE (q + k, in place)
    {
        int total = TT * 40 * 64;
        rope_kernel<<<(total + 255) / 256, 256>>>(qkv_buf, cosp, sinp);
    }
    // 3) cache scatter (last-writer-wins)
    owner_init_kernel<<<(CACHE + 255) / 256, 256>>>();
    owner_scatter_kernel<<<(TT + 255) / 256, 256>>>(slots);
    {
        int total = TT * KVH * DD;
        cache_write_kernel<<<(total + 255) / 256, 256>>>(qkv_buf, slots, kout, vout);
    }
    // 4) flash attention
    {
        static_assert(ATTN_SMEM_BYTES == 115456, "smem size");
        cudaFuncSetAttribute(attn_kernel, cudaFuncAttributeMaxDynamicSharedMemorySize,
                             ATTN_SMEM_BYTES);
        dim3 grid(SS / 64, HH, BB);
        attn_kernel<<<grid, 256, ATTN_SMEM_BYTES>>>(qkv_buf, attn_buf);
    }
    // 5) output projection (tensor cores, split-bf16)
    {
        dim3 grid(HID / 128, TT / 128);
        gemm_bf16split_nt_bias<<<grid, 256>>>(TT, HID, HID, attn_buf, w_o, b_o, out);
    }
}

// round 3
// speedup vs baseline: 1.2816x; 1.2816x over previous
#include <cuda_runtime.h>
#include <cuda_bf16.h>
#include <math.h>
#include <stdint.h>

// ---------------------------------------------------------------------------
// Problem constants (fixed shapes from the reference)
// ---------------------------------------------------------------------------
#define HH     32          // query heads
#define KVH    8           // kv heads
#define DD     128         // head dim
#define HID    (HH * DD)   // 4096
#define NQK    (HID + 2 * KVH * DD)  // 6144
#define BB     4
#define SS     1024
#define TT     (BB * SS)   // 4096
#define CACHE  16384
#define GRP    (HH / KVH)  // 4

// ---------------------------------------------------------------------------
// Scratch (device globals; no allocations allowed)
// ---------------------------------------------------------------------------
__device__ float g_qkv[(size_t)TT * NQK];    // 100.7 MB: qkv projection (post-rope)
__device__ float g_attn[(size_t)TT * HID];   // 67 MB:  attention output (bqhd flat)
__device__ int   g_owner[CACHE];             // last-writer-wins owner per cache slot

// ---------------------------------------------------------------------------
// Common helpers
// ---------------------------------------------------------------------------
__device__ __forceinline__ uint32_t pack_bf2(__nv_bfloat16 a, __nv_bfloat16 b) {
    return (uint32_t)__bfloat16_as_ushort(a) | ((uint32_t)__bfloat16_as_ushort(b) << 16);
}

__device__ __forceinline__ void ldsm_x4(uint32_t& r0, uint32_t& r1,
                                        uint32_t& r2, uint32_t& r3, uint32_t addr) {
    asm volatile("ldmatrix.sync.aligned.m8n8.x4.shared.b16 {%0,%1,%2,%3}, [%4];"
                 : "=r"(r0), "=r"(r1), "=r"(r2), "=r"(r3) : "r"(addr));
}

__device__ __forceinline__ void ldsm_x4_trans(uint32_t& r0, uint32_t& r1,
                                              uint32_t& r2, uint32_t& r3, uint32_t addr) {
    asm volatile("ldmatrix.sync.aligned.m8n8.x4.trans.shared.b16 {%0,%1,%2,%3}, [%4];"
                 : "=r"(r0), "=r"(r1), "=r"(r2), "=r"(r3) : "r"(addr));
}

__device__ __forceinline__ void mma16816(float* d, const uint32_t* a, const uint32_t* b) {
    asm volatile("mma.sync.aligned.m16n8k16.row.col.f32.bf16.bf16.f32 "
                 "{%0,%1,%2,%3}, {%4,%5,%6,%7}, {%8,%9}, {%0,%1,%2,%3};"
                 : "+f"(d[0]), "+f"(d[1]), "+f"(d[2]), "+f"(d[3])
                 : "r"(a[0]), "r"(a[1]), "r"(a[2]), "r"(a[3]), "r"(b[0]), "r"(b[1]));
}

// convert float4 -> (hi,lo) bf16 pairs and store 8B to each smem target
__device__ __forceinline__ void cvt_f4_store(float4 v, __nv_bfloat16* ph, __nv_bfloat16* pl) {
    float x[4] = {v.x, v.y, v.z, v.w};
    __nv_bfloat16 h[4], l[4];
#pragma unroll
    for (int e = 0; e < 4; e++) {
        h[e] = __float2bfloat16_rn(x[e]);
        l[e] = __float2bfloat16_rn(x[e] - __bfloat162float(h[e]));
    }
    uint32_t* hp = reinterpret_cast<uint32_t*>(ph);
    uint32_t* lp = reinterpret_cast<uint32_t*>(pl);
    hp[0] = pack_bf2(h[0], h[1]);  hp[1] = pack_bf2(h[2], h[3]);
    lp[0] = pack_bf2(l[0], l[1]);  lp[1] = pack_bf2(l[2], l[3]);
}

__device__ __forceinline__ void split_pack2(float a, float b, uint32_t& hi, uint32_t& lo) {
    __nv_bfloat16 ah = __float2bfloat16_rn(a), bh = __float2bfloat16_rn(b);
    __nv_bfloat16 al = __float2bfloat16_rn(a - __bfloat162float(ah));
    __nv_bfloat16 bl = __float2bfloat16_rn(b - __bfloat162float(bh));
    hi = pack_bf2(ah, bh);
    lo = pack_bf2(al, bl);
}

// ---------------------------------------------------------------------------
// Split-bf16 tensor-core GEMM:
//   C[M,N] = A[M,K] * B[N,K]^T + bias[N]   (A,B row-major, K contiguous)
// fp32 x = hi(bf16) + lo(bf16); accumulate hi*hi + hi*lo + lo*hi in fp32.
// BM=BN=128, BK=32, 256 threads, 8 warps (2x4), warp tile 64x32,
// mma.sync.m16n8k16, ldmatrix from stride-40 (80B) padded smem (conflict-free).
// ---------------------------------------------------------------------------
#define GPAD 40   // bf16 elements per smem row (32 data + 8 pad)

__global__ __launch_bounds__(256)
void gemm_bf16split_nt_bias(int M, int N, int K,
                            const float* __restrict__ A,
                            const float* __restrict__ B,
                            const float* __restrict__ bias,
                            float* __restrict__ C)
{
    __shared__ __align__(16) __nv_bfloat16 Ah[128 * GPAD];
    __shared__ __align__(16) __nv_bfloat16 Al[128 * GPAD];
    __shared__ __align__(16) __nv_bfloat16 Bh[128 * GPAD];
    __shared__ __align__(16) __nv_bfloat16 Bl[128 * GPAD];

    const int tid  = threadIdx.x;
    const int lane = tid & 31;
    const int wid  = tid >> 5;
    const int wm   = wid & 1;          // 0..1  (64-row strip)
    const int wn   = wid >> 1;         // 0..3  (32-col strip)
    const int bm   = blockIdx.y * 128;
    const int bn   = blockIdx.x * 128;

    const uint32_t ah_s = (uint32_t)__cvta_generic_to_shared(Ah);
    const uint32_t al_s = (uint32_t)__cvta_generic_to_shared(Al);
    const uint32_t bh_s = (uint32_t)__cvta_generic_to_shared(Bh);
    const uint32_t bl_s = (uint32_t)__cvta_generic_to_shared(Bl);

    float acc[4][4][4];
#pragma unroll
    for (int mt = 0; mt < 4; mt++)
#pragma unroll
        for (int nt = 0; nt < 4; nt++)
#pragma unroll
            for (int r = 0; r < 4; r++) acc[mt][nt][r] = 0.0f;

    // gmem prefetch registers: 4 float4 of A + 4 of B per thread per chunk
    float4 pa[4], pb[4];
#pragma unroll
    for (int l = 0; l < 4; l++) {
        int id  = tid + l * 256;        // 0..1023
        int row = id >> 3;
        int c4  = (id & 7) << 2;
        pa[l] = *reinterpret_cast<const float4*>(&A[(size_t)(bm + row) * K + c4]);
        pb[l] = *reinterpret_cast<const float4*>(&B[(size_t)(bn + row) * K + c4]);
    }

    for (int k0 = 0; k0 < K; k0 += 32) {
        // stage: convert fp32 -> (hi, lo) bf16 and store to smem
#pragma unroll
        for (int l = 0; l < 4; l++) {
            int id  = tid + l * 256;
            int row = id >> 3;
            int c4  = (id & 7) << 2;
            cvt_f4_store(pa[l], &Ah[row * GPAD + c4], &Al[row * GPAD + c4]);
            cvt_f4_store(pb[l], &Bh[row * GPAD + c4], &Bl[row * GPAD + c4]);
        }
        __syncthreads();

        // prefetch next chunk from gmem while computing this one
        if (k0 + 32 < K) {
#pragma unroll
            for (int l = 0; l < 4; l++) {
                int id  = tid + l * 256;
                int row = id >> 3;
                int c4  = (id & 7) << 2;
                pa[l] = *reinterpret_cast<const float4*>(&A[(size_t)(bm + row) * K + k0 + 32 + c4]);
                pb[l] = *reinterpret_cast<const float4*>(&B[(size_t)(bn + row) * K + k0 + 32 + c4]);
            }
        }

        // ldmatrix lane geometry (shared by A and B loads)
        const int lrow = (lane & 7) + ((lane >> 3) & 1) * 8;   // row within 16-row tile
        const int lcol = (lane >> 4) * 8;                      // 0 or 8 (k-offset)

#pragma unroll
        for (int ks = 0; ks < 32; ks += 16) {
            uint32_t a_h[4][4], a_l[4][4], b_h[4][2], b_l[4][2];
#pragma unroll
            for (int mt = 0; mt < 4; mt++) {
                uint32_t off = (uint32_t)(((wm * 64 + mt * 16 + lrow) * GPAD + ks + lcol) * 2);
                ldsm_x4(a_h[mt][0], a_h[mt][1], a_h[mt][2], a_h[mt][3], ah_s + off);
                ldsm_x4(a_l[mt][0], a_l[mt][1], a_l[mt][2], a_l[mt][3], al_s + off);
            }
#pragma unroll
            for (int p = 0; p < 2; p++) {
                uint32_t off = (uint32_t)(((wn * 32 + p * 16 + lrow) * GPAD + ks + lcol) * 2);
                uint32_t r0, r1, r2, r3;
                ldsm_x4(r0, r1, r2, r3, bh_s + off);
                b_h[2 * p][0] = r0; b_h[2 * p][1] = r2;
                b_h[2 * p + 1][0] = r1; b_h[2 * p + 1][1] = r3;
                ldsm_x4(r0, r1, r2, r3, bl_s + off);
                b_l[2 * p][0] = r0; b_l[2 * p][1] = r2;
                b_l[2 * p + 1][0] = r1; b_l[2 * p + 1][1] = r3;
            }
#pragma unroll
            for (int mt = 0; mt < 4; mt++)
#pragma unroll
                for (int nt = 0; nt < 4; nt++) {
                    mma16816(acc[mt][nt], a_h[mt], b_h[nt]);   // hi*hi
                    mma16816(acc[mt][nt], a_h[mt], b_l[nt]);   // hi*lo
                    mma16816(acc[mt][nt], a_l[mt], b_h[nt]);   // lo*hi
                }
        }
        __syncthreads();
    }

    // epilogue: add bias, write C
#pragma unroll
    for (int mt = 0; mt < 4; mt++) {
        int row = bm + wm * 64 + mt * 16 + (lane >> 2);
#pragma unroll
        for (int nt = 0; nt < 4; nt++) {
            int col = bn + wn * 32 + nt * 8 + (lane & 3) * 2;
            float b0 = bias[col], b1 = bias[col + 1];
            float2 v0 = make_float2(acc[mt][nt][0] + b0, acc[mt][nt][1] + b1);
            float2 v1 = make_float2(acc[mt][nt][2] + b0, acc[mt][nt][3] + b1);
            *reinterpret_cast<float2*>(&C[(size_t)row * N + col])       = v0;
            *reinterpret_cast<float2*>(&C[(size_t)(row + 8) * N + col]) = v1;
        }
    }
}

// ---------------------------------------------------------------------------
// RoPE in-place on q (heads 0..31) and k (heads 32..39) of g_qkv
// ---------------------------------------------------------------------------
__global__ void rope_kernel(float* __restrict__ qkv,
                            const float* __restrict__ cosp,
                            const float* __restrict__ sinp)
{
    int idx = blockIdx.x * blockDim.x + threadIdx.x;  // TT * 40 * 64
    if (idx >= TT * 40 * 64) return;
    int i = idx & 63;
    int h = (idx >> 6) % 40;
    int t = idx / (40 * 64);
    float c = cosp[t * 64 + i];
    float s = sinp[t * 64 + i];
    float* base = qkv + (size_t)t * NQK + h * DD;
    float x1 = base[i];
    float x2 = base[i + 64];
    base[i]      = x1 * c - x2 * s;
    base[i + 64] = x2 * c + x1 * s;
}

// ---------------------------------------------------------------------------
// Cache scatter with last-writer-wins (sequential .at[].set semantics)
// ---------------------------------------------------------------------------
__global__ void owner_init_kernel()
{
    int i = blockIdx.x * blockDim.x + threadIdx.x;
    if (i < CACHE) g_owner[i] = -1;
}

__global__ void owner_scatter_kernel(const int* __restrict__ slots)
{
    int t = blockIdx.x * blockDim.x + threadIdx.x;
    if (t < TT) atomicMax(&g_owner[slots[t]], t);
}

__global__ void cache_write_kernel(const float* __restrict__ qkv,
                                   const int* __restrict__ slots,
                                   float* __restrict__ kout,
                                   float* __restrict__ vout)
{
    int idx = blockIdx.x * blockDim.x + threadIdx.x;  // TT * 1024
    if (idx >= TT * KVH * DD) return;
    int t = idx >> 10;
    int j = idx & 1023;
    int slot = slots[t];
    if (g_owner[slot] != t) return;
    kout[(size_t)slot * (KVH * DD) + j] = qkv[(size_t)t * NQK + HID + j];
    vout[(size_t)slot * (KVH * DD) + j] = qkv[(size_t)t * NQK + HID + KVH * DD + j];
}

// ---------------------------------------------------------------------------
// Flash attention v2: tensor cores, full split-bf16 (Q,K,P,V hi/lo; 3 chains).
// One CTA = (batch, head, 64-row q tile). 128 threads = 4 warps; warp w owns
// rows 16w..16w+15 and ALL 64 kv-cols -> softmax warp-local via shfl.
// S accumulator repacked in-register as P's A-fragment (no smem round trip).
// V consumed via ldmatrix.trans from natural [j][d] layout.
// smem: 6 tiles of [64][136] bf16 = 104448 B -> 2 CTAs/SM co-resident.
// ---------------------------------------------------------------------------
#define AQP 136
#define ATTN2_SMEM_BYTES (6 * 64 * AQP * 2)

__global__ __launch_bounds__(128)
void attn_tc_kernel(const float* __restrict__ qkv, float* __restrict__ attn_out)
{
    extern __shared__ __align__(16) char smraw[];
    __nv_bfloat16* Qh = reinterpret_cast<__nv_bfloat16*>(smraw);
    __nv_bfloat16* Ql = Qh + 64 * AQP;
    __nv_bfloat16* Kh = Ql + 64 * AQP;
    __nv_bfloat16* Kl = Kh + 64 * AQP;
    __nv_bfloat16* Vh = Kl + 64 * AQP;
    __nv_bfloat16* Vl = Vh + 64 * AQP;

    const int qt = blockIdx.x;          // 0..15
    const int h  = blockIdx.y;          // 0..31
    const int b  = blockIdx.z;          // 0..3
    const int tid  = threadIdx.x;
    const int lane = tid & 31;
    const int w    = tid >> 5;          // warp id: 16-row strip

    const int qoff = h * DD;
    const int koff = HID + (h >> 2) * DD;
    const int voff = HID + KVH * DD + (h >> 2) * DD;
    const float scale = 0.08838834764831845f;  // 1/sqrt(128)

    const uint32_t qh_s = (uint32_t)__cvta_generic_to_shared(Qh);
    const uint32_t ql_s = (uint32_t)__cvta_generic_to_shared(Ql);
    const uint32_t kh_s = (uint32_t)__cvta_generic_to_shared(Kh);
    const uint32_t kl_s = (uint32_t)__cvta_generic_to_shared(Kl);
    const uint32_t vh_s = (uint32_t)__cvta_generic_to_shared(Vh);
    const uint32_t vl_s = (uint32_t)__cvta_generic_to_shared(Vl);

    // load Q tile once (64 x 128 fp32 -> hi/lo bf16)
#pragma unroll
    for (int l = 0; l < 16; l++) {
        int id  = tid + l * 128;        // 0..2047
        int row = id >> 5;
        int c4  = (id & 31) * 4;
        float4 v = *reinterpret_cast<const float4*>(
            &qkv[(size_t)(b * SS + qt * 64 + row) * NQK + qoff + c4]);
        cvt_f4_store(v, &Qh[row * AQP + c4], &Ql[row * AQP + c4]);
    }

    float o[16][4];
#pragma unroll
    for (int t = 0; t < 16; t++)
#pragma unroll
        for (int k = 0; k < 4; k++) o[t][k] = 0.0f;
    float mrow0 = -INFINITY, mrow1 = -INFINITY;
    float lrw0 = 0.0f, lrw1 = 0.0f;

    // ldmatrix lane geometry
    const int lra = (lane & 7) + ((lane >> 3) & 1) * 8;
    const int lca = (lane >> 4) * 8;

    for (int jt = 0; jt <= qt; jt++) {
        __syncthreads();   // prior iteration's smem readers done (also orders Q stores)
        // load K, V tiles (64 x 128 fp32 each -> hi/lo bf16)
#pragma unroll
        for (int l = 0; l < 16; l++) {
            int id  = tid + l * 128;
            int row = id >> 5;
            int c4  = (id & 31) * 4;
            size_t base = (size_t)(b * SS + jt * 64 + row) * NQK;
            float4 kv4 = *reinterpret_cast<const float4*>(&qkv[base + koff + c4]);
            cvt_f4_store(kv4, &Kh[row * AQP + c4], &Kl[row * AQP + c4]);
            float4 vv4 = *reinterpret_cast<const float4*>(&qkv[base + voff + c4]);
            cvt_f4_store(vv4, &Vh[row * AQP + c4], &Vl[row * AQP + c4]);
        }
        __syncthreads();

        // ---- S = Q K^T  (warp tile 16x64, k=128: 8 k16 steps, 3 chains) ----
        float sacc[8][4];
#pragma unroll
        for (int t = 0; t < 8; t++)
#pragma unroll
            for (int k = 0; k < 4; k++) sacc[t][k] = 0.0f;

#pragma unroll
        for (int kt = 0; kt < 8; kt++) {
            uint32_t ah[4], al[4];
            uint32_t aoff = (uint32_t)(((16 * w + lra) * AQP + 16 * kt + lca) * 2);
            ldsm_x4(ah[0], ah[1], ah[2], ah[3], qh_s + aoff);
            ldsm_x4(al[0], al[1], al[2], al[3], ql_s + aoff);
#pragma unroll
            for (int nt2 = 0; nt2 < 4; nt2++) {
                uint32_t boff = (uint32_t)(((16 * nt2 + lra) * AQP + 16 * kt + lca) * 2);
                uint32_t r0, r1, r2, r3;
                ldsm_x4(r0, r1, r2, r3, kh_s + boff);
                uint32_t bh0[2] = {r0, r2}, bh1[2] = {r1, r3};
                ldsm_x4(r0, r1, r2, r3, kl_s + boff);
                uint32_t bl0[2] = {r0, r2}, bl1[2] = {r1, r3};
                mma16816(sacc[2 * nt2],     ah, bh0);
                mma16816(sacc[2 * nt2],     ah, bl0);
                mma16816(sacc[2 * nt2],     al, bh0);
                mma16816(sacc[2 * nt2 + 1], ah, bh1);
                mma16816(sacc[2 * nt2 + 1], ah, bl1);
                mma16816(sacc[2 * nt2 + 1], al, bh1);
            }
        }

        // ---- scale + causal mask ----
        const bool diag = (jt == qt);
        const int rl = lane >> 2;
#pragma unroll
        for (int t = 0; t < 8; t++)
#pragma unroll
            for (int k = 0; k < 4; k++) {
                float v = sacc[t][k] * scale;
                if (diag) {
                    int c = 8 * t + 2 * (lane & 3) + (k & 1);
                    int r = 16 * w + rl + ((k >= 2) ? 8 : 0);
                    if (c > r) v = -1e30f;
                }
                sacc[t][k] = v;
            }

        // ---- online softmax (warp-local rows) ----
        float mx0 = -INFINITY, mx1 = -INFINITY;
#pragma unroll
        for (int t = 0; t < 8; t++) {
            mx0 = fmaxf(mx0, fmaxf(sacc[t][0], sacc[t][1]));
            mx1 = fmaxf(mx1, fmaxf(sacc[t][2], sacc[t][3]));
        }
        mx0 = fmaxf(mx0, __shfl_xor_sync(0xffffffffu, mx0, 1));
        mx0 = fmaxf(mx0, __shfl_xor_sync(0xffffffffu, mx0, 2));
        mx1 = fmaxf(mx1, __shfl_xor_sync(0xffffffffu, mx1, 1));
        mx1 = fmaxf(mx1, __shfl_xor_sync(0xffffffffu, mx1, 2));

        float mn0 = fmaxf(mrow0, mx0), mn1 = fmaxf(mrow1, mx1);
        float al0 = __expf(mrow0 - mn0), al1 = __expf(mrow1 - mn1);
        mrow0 = mn0; mrow1 = mn1;

        float s0 = 0.0f, s1 = 0.0f;
#pragma unroll
        for (int t = 0; t < 8; t++) {
            float p0 = __expf(sacc[t][0] - mn0);
            float p1 = __expf(sacc[t][1] - mn0);
            float p2 = __expf(sacc[t][2] - mn1);
            float p3 = __expf(sacc[t][3] - mn1);
            sacc[t][0] = p0; sacc[t][1] = p1; sacc[t][2] = p2; sacc[t][3] = p3;
            s0 += p0 + p1; s1 += p2 + p3;
        }
        s0 += __shfl_xor_sync(0xffffffffu, s0, 1);
        s0 += __shfl_xor_sync(0xffffffffu, s0, 2);
        s1 += __shfl_xor_sync(0xffffffffu, s1, 1);
        s1 += __shfl_xor_sync(0xffffffffu, s1, 2);
        lrw0 = lrw0 * al0 + s0;
        lrw1 = lrw1 * al1 + s1;

#pragma unroll
        for (int t = 0; t < 16; t++) {
            o[t][0] *= al0; o[t][1] *= al0;
            o[t][2] *= al1; o[t][3] *= al1;
        }

        // ---- repack P (accumulator layout == A-fragment layout) ----
        uint32_t phi[4][4], plo[4][4];
#pragma unroll
        for (int kt = 0; kt < 4; kt++) {
            int t0 = 2 * kt, t1 = t0 + 1;
            split_pack2(sacc[t0][0], sacc[t0][1], phi[kt][0], plo[kt][0]);
            split_pack2(sacc[t0][2], sacc[t0][3], phi[kt][1], plo[kt][1]);
            split_pack2(sacc[t1][0], sacc[t1][1], phi[kt][2], plo[kt][2]);
            split_pack2(sacc[t1][2], sacc[t1][3], phi[kt][3], plo[kt][3]);
        }

        // ---- O += P V  (warp tile 16x128, k=64: 4 k16 steps, 3 chains) ----
#pragma unroll
        for (int kt = 0; kt < 4; kt++) {
#pragma unroll
            for (int nt2 = 0; nt2 < 8; nt2++) {
                uint32_t vo = (uint32_t)(((16 * kt + lra) * AQP + 16 * nt2 + lca) * 2);
                uint32_t r0, r1, r2, r3;
                ldsm_x4_trans(r0, r1, r2, r3, vh_s + vo);
                uint32_t bh0[2] = {r0, r1}, bh1[2] = {r2, r3};
                ldsm_x4_trans(r0, r1, r2, r3, vl_s + vo);
                uint32_t bl0[2] = {r0, r1}, bl1[2] = {r2, r3};
                mma16816(o[2 * nt2],     phi[kt], bh0);
                mma16816(o[2 * nt2],     phi[kt], bl0);
                mma16816(o[2 * nt2],     plo[kt], bh0);
                mma16816(o[2 * nt2 + 1], phi[kt], bh1);
                mma16816(o[2 * nt2 + 1], phi[kt], bl1);
                mma16816(o[2 * nt2 + 1], plo[kt], bh1);
            }
        }
    }

    // ---- normalize + store ----
    float inv0 = 1.0f / lrw0, inv1 = 1.0f / lrw1;
    int r0g = b * SS + qt * 64 + 16 * w + (lane >> 2);
#pragma unroll
    for (int t = 0; t < 16; t++) {
        int d = 8 * t + 2 * (lane & 3);
        *reinterpret_cast<float2*>(&attn_out[(size_t)r0g * HID + h * DD + d]) =
            make_float2(o[t][0] * inv0, o[t][1] * inv0);
        *reinterpret_cast<float2*>(&attn_out[(size_t)(r0g + 8) * HID + h * DD + d]) =
            make_float2(o[t][2] * inv1, o[t][3] * inv1);
    }
}

// ---------------------------------------------------------------------------
// kernel_launch
// ---------------------------------------------------------------------------
extern "C" void kernel_launch(void* const* d_in, const int* in_sizes, int n_in,
                              void* d_out, int out_size)
{
    const float* hidden = (const float*)d_in[0];
    const float* cosp   = (const float*)d_in[1];
    const float* sinp   = (const float*)d_in[2];
    const float* w_qkv  = (const float*)d_in[3];
    const float* b_qkv  = (const float*)d_in[4];
    const float* w_o    = (const float*)d_in[5];
    const float* b_o    = (const float*)d_in[6];
    const float* kc_in  = (const float*)d_in[7];
    const float* vc_in  = (const float*)d_in[8];
    const int*   slots  = (const int*)d_in[9];

    float* out  = (float*)d_out;
    float* kout = out + (size_t)TT * HID;
    float* vout = kout + (size_t)CACHE * KVH * DD;

    float* qkv_buf;
    float* attn_buf;
    cudaGetSymbolAddress((void**)&qkv_buf, g_qkv);
    cudaGetSymbolAddress((void**)&attn_buf, g_attn);

    const size_t cache_bytes = (size_t)CACHE * KVH * DD * sizeof(float);
    cudaMemcpyAsync(kout, kc_in, cache_bytes, cudaMemcpyDeviceToDevice);
    cudaMemcpyAsync(vout, vc_in, cache_bytes, cudaMemcpyDeviceToDevice);

    // 1) QKV projection (tensor cores, split-bf16)
    {
        dim3 grid(NQK / 128, TT / 128);
        gemm_bf16split_nt_bias<<<grid, 256>>>(TT, NQK, HID, hidden, w_qkv, b_qkv, qkv_buf);
    }
    // 2) RoPE (q + k, in place)
    {
        int total = TT * 40 * 64;
        rope_kernel<<<(total + 255) / 256, 256>>>(qkv_buf, cosp, sinp);
    }
    // 3) cache scatter (last-writer-wins)
    owner_init_kernel<<<(CACHE + 255) / 256, 256>>>();
    owner_scatter_kernel<<<(TT + 255) / 256, 256>>>(slots);
    {
        int total = TT * KVH * DD;
        cache_write_kernel<<<(total + 255) / 256, 256>>>(qkv_buf, slots, kout, vout);
    }
    // 4) flash attention (tensor cores, full split-bf16)
    {
        cudaFuncSetAttribute(attn_tc_kernel, cudaFuncAttributeMaxDynamicSharedMemorySize,
                             ATTN2_SMEM_BYTES);
        dim3 grid(SS / 64, HH, BB);
        attn_tc_kernel<<<grid, 128, ATTN2_SMEM_BYTES>>>(qkv_buf, attn_buf);
    }
    // 5) output projection (tensor cores, split-bf16)
    {
        dim3 grid(HID / 128, TT / 128);
        gemm_bf16split_nt_bias<<<grid, 256>>>(TT, HID, HID, attn_buf, w_o, b_o, out);
    }
}